// round 10
// baseline (speedup 1.0000x reference)
#include <cuda_runtime.h>
#include <cuda_bf16.h>
#include <cstdint>

#define F        128
#define N_ATOMS  8192
#define TILE_M   64
#define TILEB    32768        // prepped weight tile: 128 rows * 256B

// pair kernel (N-split, 2 CTAs/SM)
#define PTHREADS 256
// atom kernels (full-width)
#define ATHREADS 512

// ---------------------------------------------------------------------------
// Device-global scratch (no allocations allowed)
// ---------------------------------------------------------------------------
__device__ float g_PS[N_ATOMS * F];   // segment-summed pair activations
__device__ float g_AA[N_ATOMS * F];   // atom layer-1 output
// Prepped weights: bf16, B-orientation [n][k], 256B rows, XOR-swizzled chunks,
// hi/lo split. 16 tiles of 32768B:
//  0:W2aH 1:W2aL 2:W2bH 3:W2bL  4:W1aH 5:W1aL 6:W1bH 7:W1bL
//  8..11: W3 chunk0 (aH,aL,bH,bL)  12..15: W3 chunk1
__device__ __align__(256) unsigned char g_Wp[16 * TILEB];

// ---- pair kernel SMEM map (per CTA, 2 CTAs/SM) ----
//  [0,65536)      4 weight slice tiles of 16KB (aH, aL, bH, bL), 64 rows each
//  [65536,81920)  X hi bf16 (64 rows x 256B)
//  [81920,98304)  X lo bf16
//  [98304,99840)  bias: ba[128], bb[128], t[128]
#define P_XH     65536
#define P_XL     81920
#define P_BIAS   98304
#define P_SMEM   99840

// ---- atom kernel SMEM map (1 CTA/SM) ----
#define A_XH     131072
#define A_XL     147456
#define A_BIAS   163840
#define A_SMEM   165376

// ---------------------------------------------------------------------------
// PTX helpers
// ---------------------------------------------------------------------------
__device__ __forceinline__ uint32_t smem_u32(const void* p) {
    uint32_t a;
    asm("{ .reg .u64 t; cvta.to.shared.u64 t, %1; cvt.u32.u64 %0, t; }" : "=r"(a) : "l"(p));
    return a;
}
__device__ __forceinline__ void ldmx4(uint32_t* r, uint32_t addr) {
    asm volatile("ldmatrix.sync.aligned.m8n8.x4.shared.b16 {%0,%1,%2,%3}, [%4];"
                 : "=r"(r[0]), "=r"(r[1]), "=r"(r[2]), "=r"(r[3]) : "r"(addr));
}
__device__ __forceinline__ void mma16816(float* d, const uint32_t* a, uint32_t b0, uint32_t b1) {
    asm volatile(
        "mma.sync.aligned.m16n8k16.row.col.f32.bf16.bf16.f32 "
        "{%0,%1,%2,%3}, {%4,%5,%6,%7}, {%8,%9}, {%0,%1,%2,%3};"
        : "+f"(d[0]), "+f"(d[1]), "+f"(d[2]), "+f"(d[3])
        : "r"(a[0]), "r"(a[1]), "r"(a[2]), "r"(a[3]), "r"(b0), "r"(b1));
}
__device__ __forceinline__ void red_v2(float* addr, float a, float b) {
    asm volatile("red.global.add.v2.f32 [%0], {%1,%2};"
                 :: "l"(addr), "f"(a), "f"(b) : "memory");
}

// ---------------------------------------------------------------------------
// X element store: fp32 float4 -> bf16 hi/lo at swizzled (row m, k4).
// i = float4 index in [0,2048): m = i>>5 in [0,64), k4 = (i&31)*4.
// Layout: 256B rows; 16B chunk c holds k in [8c,8c+8) at chunk (c ^ (m&7)).
// ---------------------------------------------------------------------------
union B2U { __nv_bfloat162 b; uint32_t u; };

__device__ __forceinline__ void x_store(char* sm, uint32_t xh_off, uint32_t xl_off,
                                        int i, float4 v) {
    const int m = i >> 5, k4 = (i & 31) << 2;
    const uint32_t sw = (uint32_t)(m << 8) + ((uint32_t)(((k4 >> 3) ^ (m & 7))) << 4)
                      + ((uint32_t)((k4 >> 2) & 1) << 3);
    __nv_bfloat162 h0 = __float22bfloat162_rn(make_float2(v.x, v.y));
    __nv_bfloat162 h1 = __float22bfloat162_rn(make_float2(v.z, v.w));
    float2 f0 = __bfloat1622float2(h0), f1 = __bfloat1622float2(h1);
    __nv_bfloat162 l0 = __float22bfloat162_rn(make_float2(v.x - f0.x, v.y - f0.y));
    __nv_bfloat162 l1 = __float22bfloat162_rn(make_float2(v.z - f1.x, v.w - f1.y));
    B2U a, b, c, d; a.b = h0; b.b = h1; c.b = l0; d.b = l1;
    *(uint2*)(sm + xh_off + sw) = make_uint2(a.u, b.u);
    *(uint2*)(sm + xl_off + sw) = make_uint2(c.u, d.u);
}

// ---------------------------------------------------------------------------
// Unified 3-term GEMM core, warp patch 32x16, k-step double-buffered frags.
// Weight slices at wBase + {0,1,2,3}*wStride (aH, aL, bH, bL); rows 256B.
// acc layout: acc[mi][jj][4], mi in {0,1} (16-row), jj in {0,1} (8-col).
// ---------------------------------------------------------------------------
__device__ __forceinline__ void gemm_core(uint32_t wBase, uint32_t wStride,
                                          uint32_t XH, uint32_t XL,
                                          int mBase, int nBase, int r, int q,
                                          float (&accA)[2][2][4], float (&accB)[2][2][4]) {
    const int cA = q >> 1, cB = q & 1;
    const uint32_t aRow0 = (uint32_t)(mBase + r + 8 * (q & 1));
    const uint32_t bRow  = (uint32_t)(nBase + r + 8 * (q >> 1));

    uint32_t Ah[2][2][4], Al[2][2][4];
    uint32_t BaH[2][4], BaL[2][4], BbH[2][4], BbL[2][4];

#define LD_K(buf, kc) do {                                                   \
    const uint32_t oA = (uint32_t)(((cA + (kc)) ^ r) << 4);                  \
    ldmx4(Ah[buf][0], XH + (aRow0 << 8) + oA);                               \
    ldmx4(Ah[buf][1], XH + ((aRow0 + 16) << 8) + oA);                        \
    ldmx4(Al[buf][0], XL + (aRow0 << 8) + oA);                               \
    ldmx4(Al[buf][1], XL + ((aRow0 + 16) << 8) + oA);                        \
    const uint32_t oB = (bRow << 8) + (uint32_t)(((cB + (kc)) ^ r) << 4);    \
    ldmx4(BaH[buf], wBase + oB);                                             \
    ldmx4(BaL[buf], wBase + wStride + oB);                                   \
    ldmx4(BbH[buf], wBase + 2 * wStride + oB);                               \
    ldmx4(BbL[buf], wBase + 3 * wStride + oB);                               \
} while (0)

    LD_K(0, 0);
#pragma unroll
    for (int k = 0; k < 8; k++) {
        const int cur = k & 1;
        if (k < 7) LD_K(cur ^ 1, 2 * (k + 1));
#pragma unroll
        for (int mi = 0; mi < 2; mi++)
#pragma unroll
            for (int jj = 0; jj < 2; jj++) {
                mma16816(accA[mi][jj], Ah[cur][mi], BaH[cur][2 * jj], BaH[cur][2 * jj + 1]);
                mma16816(accA[mi][jj], Ah[cur][mi], BaL[cur][2 * jj], BaL[cur][2 * jj + 1]);
                mma16816(accA[mi][jj], Al[cur][mi], BaH[cur][2 * jj], BaH[cur][2 * jj + 1]);
                mma16816(accB[mi][jj], Ah[cur][mi], BbH[cur][2 * jj], BbH[cur][2 * jj + 1]);
                mma16816(accB[mi][jj], Ah[cur][mi], BbL[cur][2 * jj], BbL[cur][2 * jj + 1]);
                mma16816(accB[mi][jj], Al[cur][mi], BbH[cur][2 * jj], BbH[cur][2 * jj + 1]);
            }
    }
#undef LD_K
}

// ---------------------------------------------------------------------------
// Weight prep (+ zero g_PS). 512 blocks x 256 threads.
// ---------------------------------------------------------------------------
extern "C" __global__ void eaw_prep(const float* __restrict__ W1a, const float* __restrict__ W1b,
                                    const float* __restrict__ W2a, const float* __restrict__ W2b,
                                    const float* __restrict__ W3a, const float* __restrict__ W3b) {
    const int e = blockIdx.x * blockDim.x + threadIdx.x;
    ((float4*)g_PS)[e]          = make_float4(0.f, 0.f, 0.f, 0.f);
    ((float4*)g_PS)[e + 131072] = make_float4(0.f, 0.f, 0.f, 0.f);

    int mat, off;
    if (e < 65536) { mat = e >> 14; off = e & 16383; }
    else           { int e2 = e - 65536; mat = 4 + (e2 >> 15); off = e2 & 32767; }
    const float* W;
    switch (mat) {
        case 0: W = W2a; break; case 1: W = W2b; break;
        case 2: W = W1a; break; case 3: W = W1b; break;
        case 4: W = W3a; break; default: W = W3b; break;
    }
    const int n = off & 127, k = off >> 7;     // W[k][n] at W[off] (coalesced)
    const float v = W[off];
    const __nv_bfloat16 h  = __float2bfloat16(v);
    const __nv_bfloat16 lo = __float2bfloat16(v - __bfloat162float(h));
    const int p = k >> 7, kk = k & 127;
    int hiTile;
    switch (mat) {
        case 0: hiTile = 0; break; case 1: hiTile = 2; break;
        case 2: hiTile = 4; break; case 3: hiTile = 6; break;
        case 4: hiTile = 8 + 4 * p;  break;
        default: hiTile = 10 + 4 * p; break;
    }
    const size_t pos = ((size_t)n << 8) + ((size_t)((kk >> 3) ^ (n & 7)) << 4) + ((size_t)(kk & 7) << 1);
    *(__nv_bfloat16*)(g_Wp + (size_t)hiTile * TILEB + pos)       = h;
    *(__nv_bfloat16*)(g_Wp + (size_t)(hiTile + 1) * TILEB + pos) = lo;
}

// ---------------------------------------------------------------------------
// Pair branch, N-split: 296 persistent CTAs (2/SM), 256 threads, 8 warps.
// CTA pair (2i, 2i+1) handles tile stream {i, i+148, ...}; half = bid & 1
// selects output columns [64h, 64h+64) and the matching weight slice.
// ---------------------------------------------------------------------------
extern "C" __global__ void __launch_bounds__(PTHREADS, 2)
eaw_pair_mm(const float* __restrict__ FP, const int* __restrict__ split,
            const float* __restrict__ b2a, const float* __restrict__ b2b,
            const float* __restrict__ t2, int nTiles) {
    extern __shared__ __align__(1024) char sm[];
    const int tid = threadIdx.x;
    const uint32_t smb = smem_u32(sm);
    const int half = blockIdx.x & 1;

    {   // weight slices: rows [64h, 64h+64) of tiles 0..3 -> 4 x 16KB
        for (int tt = 0; tt < 4; tt++) {
            const uint4* src = (const uint4*)(g_Wp + (size_t)tt * TILEB + (size_t)half * 16384);
            uint4* dst = (uint4*)(sm + tt * 16384);
            for (int i = tid; i < 1024; i += PTHREADS) dst[i] = src[i];
        }
    }
    if (tid < 128) {
        ((float*)(sm + P_BIAS))[tid]       = b2a[tid];
        ((float*)(sm + P_BIAS))[128 + tid] = b2b[tid];
        ((float*)(sm + P_BIAS))[256 + tid] = t2[tid];
    }

    const int lane = tid & 31, w = tid >> 5;
    const int mBase = (w >> 2) * 32, nBase = (w & 3) * 16;  // 2 x 4 warp grid
    const int q = lane >> 3, r = lane & 7;
    const float* biasA = (const float*)(sm + P_BIAS);
    const float* biasB = biasA + 128;
    const float* tvv   = biasA + 256;
    const int step = gridDim.x >> 1;
    __syncthreads();   // weights/bias ready

    for (int tile = blockIdx.x >> 1; tile < nTiles; tile += step) {
        // X tile: 2048 float4, 8 per thread (LDGs issue before barrier wait)
        float4 xv[8];
        {
            const float4* src = (const float4*)(FP + (size_t)tile * (TILE_M * F));
#pragma unroll
            for (int qq = 0; qq < 8; qq++) xv[qq] = src[tid + qq * PTHREADS];
        }
        // atom indices for this tile (hidden under gemm)
        const int* sp = split + tile * TILE_M;
        int atomIdx[2][2];
#pragma unroll
        for (int mi = 0; mi < 2; mi++)
#pragma unroll
            for (int sub = 0; sub < 2; sub++)
                atomIdx[mi][sub] = sp[mBase + 16 * mi + (lane >> 2) + 8 * sub];

        __syncthreads();   // previous tile's smem X reads done
#pragma unroll
        for (int qq = 0; qq < 8; qq++)
            x_store(sm, P_XH, P_XL, tid + qq * PTHREADS, xv[qq]);
        __syncthreads();   // X ready

        float accA[2][2][4], accB[2][2][4];
#pragma unroll
        for (int mi = 0; mi < 2; mi++)
#pragma unroll
            for (int jj = 0; jj < 2; jj++)
#pragma unroll
                for (int kq = 0; kq < 4; kq++) { accA[mi][jj][kq] = 0.f; accB[mi][jj][kq] = 0.f; }

        gemm_core(smb, 16384, smb + P_XH, smb + P_XL, mBase, nBase, r, q, accA, accB);

        // epilogue: relu(t*ya*yb) -> red.v2 scatter (global cols 64h + local)
#pragma unroll
        for (int mi = 0; mi < 2; mi++)
#pragma unroll
            for (int sub = 0; sub < 2; sub++) {
                float* dst = g_PS + (size_t)atomIdx[mi][sub] * F;
#pragma unroll
                for (int jj = 0; jj < 2; jj++) {
                    const int cg = 64 * half + nBase + 8 * jj + 2 * (lane & 3);
                    const float v0 = fmaxf(tvv[cg]     * (accA[mi][jj][2 * sub]     + biasA[cg])     * (accB[mi][jj][2 * sub]     + biasB[cg]),     0.f);
                    const float v1 = fmaxf(tvv[cg + 1] * (accA[mi][jj][2 * sub + 1] + biasA[cg + 1]) * (accB[mi][jj][2 * sub + 1] + biasB[cg + 1]), 0.f);
                    red_v2(dst + cg, v0, v1);
                }
            }
    }
}

// ---------------------------------------------------------------------------
// Atom layer 1: g_AA = relu(t1*(FA@W1a+b1a)*(FA@W1b+b1b)). 128 CTAs x 64 rows,
// 512 threads, full 128-col weights (4 x 32KB tiles).
// ---------------------------------------------------------------------------
extern "C" __global__ void __launch_bounds__(ATHREADS, 1)
eaw_atom1_mm(const float* __restrict__ FA,
             const float* __restrict__ b1a, const float* __restrict__ b1b,
             const float* __restrict__ t1) {
    extern __shared__ __align__(1024) char sm[];
    const int tid = threadIdx.x;
    const uint32_t smb = smem_u32(sm);
    {
        const uint4* src = (const uint4*)(g_Wp + 4 * TILEB);
        uint4* dst = (uint4*)sm;
        for (int i = tid; i < 8192; i += ATHREADS) dst[i] = src[i];
    }
    if (tid < 128) {
        ((float*)(sm + A_BIAS))[tid]       = b1a[tid];
        ((float*)(sm + A_BIAS))[128 + tid] = b1b[tid];
        ((float*)(sm + A_BIAS))[256 + tid] = t1[tid];
    }
    {
        const float4* src = (const float4*)(FA + (size_t)blockIdx.x * (TILE_M * F));
        float4 xv[4];
#pragma unroll
        for (int qq = 0; qq < 4; qq++) xv[qq] = src[tid + qq * ATHREADS];
#pragma unroll
        for (int qq = 0; qq < 4; qq++) x_store(sm, A_XH, A_XL, tid + qq * ATHREADS, xv[qq]);
    }
    __syncthreads();

    const int lane = tid & 31, w = tid >> 5;
    const int mBase = (w >> 3) * 32, nBase = (w & 7) * 16;
    const int q = lane >> 3, r = lane & 7;
    const float* biasA = (const float*)(sm + A_BIAS);
    const float* biasB = biasA + 128;
    const float* tvv   = biasA + 256;

    float accA[2][2][4], accB[2][2][4];
#pragma unroll
    for (int mi = 0; mi < 2; mi++)
#pragma unroll
        for (int jj = 0; jj < 2; jj++)
#pragma unroll
            for (int kq = 0; kq < 4; kq++) { accA[mi][jj][kq] = 0.f; accB[mi][jj][kq] = 0.f; }

    gemm_core(smb, 32768, smb + A_XH, smb + A_XL, mBase, nBase, r, q, accA, accB);

    float* base = g_AA + (size_t)blockIdx.x * (TILE_M * F);
#pragma unroll
    for (int mi = 0; mi < 2; mi++)
#pragma unroll
        for (int sub = 0; sub < 2; sub++) {
            const int row = mBase + 16 * mi + (lane >> 2) + 8 * sub;
#pragma unroll
            for (int jj = 0; jj < 2; jj++) {
                const int c = nBase + 8 * jj + 2 * (lane & 3);
                float2 v;
                v.x = fmaxf(tvv[c]     * (accA[mi][jj][2 * sub]     + biasA[c])     * (accB[mi][jj][2 * sub]     + biasB[c]),     0.f);
                v.y = fmaxf(tvv[c + 1] * (accA[mi][jj][2 * sub + 1] + biasA[c + 1]) * (accB[mi][jj][2 * sub + 1] + biasB[c + 1]), 0.f);
                *(float2*)(base + (size_t)row * F + c) = v;
            }
        }
}

// ---------------------------------------------------------------------------
// Final layer (K=256, two phases): out = relu(t3*([AA|PS]@W3a+b3a)*(...b)).
// 128 CTAs x 64 rows, 512 threads.
// ---------------------------------------------------------------------------
extern "C" __global__ void __launch_bounds__(ATHREADS, 1)
eaw_atom2_mm(const float* __restrict__ b3a, const float* __restrict__ b3b,
             const float* __restrict__ t3, float* __restrict__ out) {
    extern __shared__ __align__(1024) char sm[];
    const int tid = threadIdx.x;
    const uint32_t smb = smem_u32(sm);
    if (tid < 128) {
        ((float*)(sm + A_BIAS))[tid]       = b3a[tid];
        ((float*)(sm + A_BIAS))[128 + tid] = b3b[tid];
        ((float*)(sm + A_BIAS))[256 + tid] = t3[tid];
    }
    const int lane = tid & 31, w = tid >> 5;
    const int mBase = (w >> 3) * 32, nBase = (w & 7) * 16;
    const int q = lane >> 3, r = lane & 7;
    const float* biasA = (const float*)(sm + A_BIAS);
    const float* biasB = biasA + 128;
    const float* tvv   = biasA + 256;

    float accA[2][2][4], accB[2][2][4];
#pragma unroll
    for (int mi = 0; mi < 2; mi++)
#pragma unroll
        for (int jj = 0; jj < 2; jj++)
#pragma unroll
            for (int kq = 0; kq < 4; kq++) { accA[mi][jj][kq] = 0.f; accB[mi][jj][kq] = 0.f; }

#pragma unroll 1
    for (int p = 0; p < 2; p++) {
        if (p) __syncthreads();             // previous phase's smem reads done
        {
            const uint4* src = (const uint4*)(g_Wp + (size_t)(8 + 4 * p) * TILEB);
            uint4* dst = (uint4*)sm;
            for (int i = tid; i < 8192; i += ATHREADS) dst[i] = src[i];
        }
        {
            const float4* src = (const float4*)((p == 0 ? g_AA : g_PS) + (size_t)blockIdx.x * (TILE_M * F));
            float4 xv[4];
#pragma unroll
            for (int qq = 0; qq < 4; qq++) xv[qq] = src[tid + qq * ATHREADS];
#pragma unroll
            for (int qq = 0; qq < 4; qq++) x_store(sm, A_XH, A_XL, tid + qq * ATHREADS, xv[qq]);
        }
        __syncthreads();
        gemm_core(smb, 32768, smb + A_XH, smb + A_XL, mBase, nBase, r, q, accA, accB);
    }

    float* base = out + (size_t)blockIdx.x * (TILE_M * F);
#pragma unroll
    for (int mi = 0; mi < 2; mi++)
#pragma unroll
        for (int sub = 0; sub < 2; sub++) {
            const int row = mBase + 16 * mi + (lane >> 2) + 8 * sub;
#pragma unroll
            for (int jj = 0; jj < 2; jj++) {
                const int c = nBase + 8 * jj + 2 * (lane & 3);
                float2 v;
                v.x = fmaxf(tvv[c]     * (accA[mi][jj][2 * sub]     + biasA[c])     * (accB[mi][jj][2 * sub]     + biasB[c]),     0.f);
                v.y = fmaxf(tvv[c + 1] * (accA[mi][jj][2 * sub + 1] + biasA[c + 1]) * (accB[mi][jj][2 * sub + 1] + biasB[c + 1]), 0.f);
                *(float2*)(base + (size_t)row * F + c) = v;
            }
        }
}

// ---------------------------------------------------------------------------
// Launch
// ---------------------------------------------------------------------------
extern "C" void kernel_launch(void* const* d_in, const int* in_sizes, int n_in,
                              void* d_out, int out_size) {
    const float* FA  = (const float*)d_in[0];
    const float* FP  = (const float*)d_in[1];
    const int*   sp  = (const int*)  d_in[2];
    const float* W1a = (const float*)d_in[3];
    const float* b1a = (const float*)d_in[4];
    const float* W1b = (const float*)d_in[5];
    const float* b1b = (const float*)d_in[6];
    const float* t1  = (const float*)d_in[7];
    const float* W2a = (const float*)d_in[8];
    const float* b2a = (const float*)d_in[9];
    const float* W2b = (const float*)d_in[10];
    const float* b2b = (const float*)d_in[11];
    const float* t2  = (const float*)d_in[12];
    const float* W3a = (const float*)d_in[13];
    const float* b3a = (const float*)d_in[14];
    const float* W3b = (const float*)d_in[15];
    const float* b3b = (const float*)d_in[16];
    const float* t3  = (const float*)d_in[17];
    float* out = (float*)d_out;

    const int nPairs    = in_sizes[1] / F;             // 524288
    const int pairTiles = nPairs / TILE_M;             // 8192
    const int atomTiles = (in_sizes[0] / F) / TILE_M;  // 128

    cudaFuncSetAttribute(eaw_pair_mm,  cudaFuncAttributeMaxDynamicSharedMemorySize, P_SMEM);
    cudaFuncSetAttribute(eaw_atom1_mm, cudaFuncAttributeMaxDynamicSharedMemorySize, A_SMEM);
    cudaFuncSetAttribute(eaw_atom2_mm, cudaFuncAttributeMaxDynamicSharedMemorySize, A_SMEM);

    int nsm = 148;
    cudaDeviceGetAttribute(&nsm, cudaDevAttrMultiProcessorCount, 0);

    eaw_prep<<<512, 256>>>(W1a, W1b, W2a, W2b, W3a, W3b);
    eaw_pair_mm<<<2 * nsm, PTHREADS, P_SMEM>>>(FP, sp, b2a, b2b, t2, pairTiles);
    eaw_atom1_mm<<<atomTiles, ATHREADS, A_SMEM>>>(FA, b1a, b1b, t1);
    eaw_atom2_mm<<<atomTiles, ATHREADS, A_SMEM>>>(b3a, b3b, t3, out);
}

// round 11
// speedup vs baseline: 1.4424x; 1.4424x over previous
#include <cuda_runtime.h>
#include <cuda_fp16.h>
#include <cstdint>

#define F        128
#define THREADS  512
#define N_ATOMS  8192
#define TILE_M   64
#define TILEB    32768        // weight tile: 128 rows * 256B (fp16, swizzled)

// ---------------------------------------------------------------------------
// Device-global scratch (no allocations allowed)
// ---------------------------------------------------------------------------
__device__ float g_PS[N_ATOMS * F];   // segment-summed pair activations
__device__ float g_AA[N_ATOMS * F];   // atom layer-1 output
// Prepped weights: fp16 (round-to-nearest), B-orientation [n][k], 256B rows,
// XOR-swizzled chunks. 8 tiles of 32768B:
//  0:W2a 1:W2b  2:W1a 3:W1b  4:W3a_c0 5:W3b_c0  6:W3a_c1 7:W3b_c1
__device__ __align__(256) unsigned char g_Wp[8 * TILEB];

// SMEM map (dynamic, base 1024-aligned):
//  [0,65536)       2 weight tiles (a, b) of 32KB
//  [65536,81920)   X hi fp16 (64 rows x 256B)
//  [81920,98304)   X lo fp16
//  [98304,131072)  fp32 stage (64 rows x 128 fp32 = 32KB)
//  [131072,132608) bias: ba[128], bb[128], t[128]
#define SM_XH    65536
#define SM_XL    81920
#define SM_STG   98304
#define SM_BIAS  131072
#define SMEM_BYTES 132608

// ---------------------------------------------------------------------------
// PTX helpers
// ---------------------------------------------------------------------------
__device__ __forceinline__ uint32_t smem_u32(const void* p) {
    uint32_t a;
    asm("{ .reg .u64 t; cvta.to.shared.u64 t, %1; cvt.u32.u64 %0, t; }" : "=r"(a) : "l"(p));
    return a;
}
__device__ __forceinline__ void ldmx4(uint32_t* r, uint32_t addr) {
    asm volatile("ldmatrix.sync.aligned.m8n8.x4.shared.b16 {%0,%1,%2,%3}, [%4];"
                 : "=r"(r[0]), "=r"(r[1]), "=r"(r[2]), "=r"(r[3]) : "r"(addr));
}
__device__ __forceinline__ void mma16816(float* d, const uint32_t* a, uint32_t b0, uint32_t b1) {
    asm volatile(
        "mma.sync.aligned.m16n8k16.row.col.f32.f16.f16.f32 "
        "{%0,%1,%2,%3}, {%4,%5,%6,%7}, {%8,%9}, {%0,%1,%2,%3};"
        : "+f"(d[0]), "+f"(d[1]), "+f"(d[2]), "+f"(d[3])
        : "r"(a[0]), "r"(a[1]), "r"(a[2]), "r"(a[3]), "r"(b0), "r"(b1));
}
__device__ __forceinline__ void red_v2(float* addr, float a, float b) {
    asm volatile("red.global.add.v2.f32 [%0], {%1,%2};"
                 :: "l"(addr), "f"(a), "f"(b) : "memory");
}
__device__ __forceinline__ void cpa16(uint32_t saddr, const void* g) {
    asm volatile("cp.async.cg.shared.global [%0], [%1], 16;" :: "r"(saddr), "l"(g));
}
__device__ __forceinline__ void cpa_commit() {
    asm volatile("cp.async.commit_group;" ::: "memory");
}
__device__ __forceinline__ void cpa_wait0() {
    asm volatile("cp.async.wait_group 0;" ::: "memory");
}

// ---------------------------------------------------------------------------
// X element store: fp32 float4 -> fp16 hi/lo at swizzled (row m, k4).
// i = float4 index in [0,2048): m = i>>5 in [0,64), k4 = (i&31)*4.
// Layout: 256B rows; 16B chunk c holds k in [8c,8c+8) at chunk (c ^ (m&7)).
// Xh+Xl reproduces X to ~2^-22 relative, so X @ W_fp16 is the only error.
// ---------------------------------------------------------------------------
union H2U { __half2 h; uint32_t u; };

__device__ __forceinline__ void x_store(char* sm, int i, float4 v) {
    const int m = i >> 5, k4 = (i & 31) << 2;
    const uint32_t sw = (uint32_t)(m << 8) + ((uint32_t)(((k4 >> 3) ^ (m & 7))) << 4)
                      + ((uint32_t)((k4 >> 2) & 1) << 3);
    __half2 h0 = __floats2half2_rn(v.x, v.y);
    __half2 h1 = __floats2half2_rn(v.z, v.w);
    float2 f0 = __half22float2(h0), f1 = __half22float2(h1);
    __half2 l0 = __floats2half2_rn(v.x - f0.x, v.y - f0.y);
    __half2 l1 = __floats2half2_rn(v.z - f1.x, v.w - f1.y);
    H2U a, b, c, d; a.h = h0; b.h = h1; c.h = l0; d.h = l1;
    *(uint2*)(sm + SM_XH + sw) = make_uint2(a.u, b.u);
    *(uint2*)(sm + SM_XL + sw) = make_uint2(c.u, d.u);
}

// ---------------------------------------------------------------------------
// 2-term GEMM for both denses, single k-loop, double-buffered fragments.
// Weight tiles at wBase (a) and wBase+32768 (b). Warp patch 32x16.
// acc layout: acc[mi][jj][4], mi in {0,1} (16-row), jj in {0,1} (8-col).
// ---------------------------------------------------------------------------
__device__ __forceinline__ void gemm_uni(uint32_t wBase, uint32_t XH, uint32_t XL,
                                         int mBase, int nBase, int r, int q,
                                         float (&accA)[2][2][4], float (&accB)[2][2][4]) {
    const int cA = q >> 1, cB = q & 1;
    const uint32_t aRow0 = (uint32_t)(mBase + r + 8 * (q & 1));
    const uint32_t bRow  = (uint32_t)(nBase + r + 8 * (q >> 1));

    uint32_t Ah[2][2][4], Al[2][2][4];
    uint32_t Ba[2][4], Bb[2][4];

#define LD_K(buf, kc) do {                                                   \
    const uint32_t oA = (uint32_t)(((cA + (kc)) ^ r) << 4);                  \
    ldmx4(Ah[buf][0], XH + (aRow0 << 8) + oA);                               \
    ldmx4(Ah[buf][1], XH + ((aRow0 + 16) << 8) + oA);                        \
    ldmx4(Al[buf][0], XL + (aRow0 << 8) + oA);                               \
    ldmx4(Al[buf][1], XL + ((aRow0 + 16) << 8) + oA);                        \
    const uint32_t oB = (bRow << 8) + (uint32_t)(((cB + (kc)) ^ r) << 4);    \
    ldmx4(Ba[buf], wBase + oB);                                              \
    ldmx4(Bb[buf], wBase + 32768 + oB);                                      \
} while (0)

    LD_K(0, 0);
#pragma unroll
    for (int k = 0; k < 8; k++) {
        const int cur = k & 1;
        if (k < 7) LD_K(cur ^ 1, 2 * (k + 1));
#pragma unroll
        for (int mi = 0; mi < 2; mi++)
#pragma unroll
            for (int jj = 0; jj < 2; jj++) {
                mma16816(accA[mi][jj], Ah[cur][mi], Ba[cur][2 * jj], Ba[cur][2 * jj + 1]);
                mma16816(accA[mi][jj], Al[cur][mi], Ba[cur][2 * jj], Ba[cur][2 * jj + 1]);
                mma16816(accB[mi][jj], Ah[cur][mi], Bb[cur][2 * jj], Bb[cur][2 * jj + 1]);
                mma16816(accB[mi][jj], Al[cur][mi], Bb[cur][2 * jj], Bb[cur][2 * jj + 1]);
            }
    }
#undef LD_K
}

// Stage helpers: 64-row tile = 2048 float4, 4 per thread.
__device__ __forceinline__ void stage_fetch(uint32_t smb, const float* __restrict__ src, int tid) {
#pragma unroll
    for (int qq = 0; qq < 4; qq++) {
        const int sidx = tid + qq * THREADS;
        cpa16(smb + SM_STG + (uint32_t)sidx * 16, src + (size_t)sidx * 4);
    }
    cpa_commit();
}
__device__ __forceinline__ void stage_convert(char* sm, int tid) {
    const float4* st = (const float4*)(sm + SM_STG);
#pragma unroll
    for (int qq = 0; qq < 4; qq++) {
        const int sidx = tid + qq * THREADS;
        x_store(sm, sidx, st[sidx]);
    }
}

// ---------------------------------------------------------------------------
// Weight prep (+ zero g_PS): fp16 round-to-nearest, B-orientation, swizzled.
// 512 blocks x 256 threads = 131072 elements.
// ---------------------------------------------------------------------------
extern "C" __global__ void eaw_prep(const float* __restrict__ W1a, const float* __restrict__ W1b,
                                    const float* __restrict__ W2a, const float* __restrict__ W2b,
                                    const float* __restrict__ W3a, const float* __restrict__ W3b) {
    const int e = blockIdx.x * blockDim.x + threadIdx.x;
    ((float4*)g_PS)[e]          = make_float4(0.f, 0.f, 0.f, 0.f);
    ((float4*)g_PS)[e + 131072] = make_float4(0.f, 0.f, 0.f, 0.f);

    int mat, off;
    if (e < 65536) { mat = e >> 14; off = e & 16383; }
    else           { int e2 = e - 65536; mat = 4 + (e2 >> 15); off = e2 & 32767; }
    const float* W;
    switch (mat) {
        case 0: W = W2a; break; case 1: W = W2b; break;
        case 2: W = W1a; break; case 3: W = W1b; break;
        case 4: W = W3a; break; default: W = W3b; break;
    }
    const int n = off & 127, k = off >> 7;     // W[k][n] at W[off] (coalesced)
    const __half h = __float2half_rn(W[off]);
    const int p = k >> 7, kk = k & 127;
    int tileIdx;
    switch (mat) {
        case 0: tileIdx = 0; break; case 1: tileIdx = 1; break;
        case 2: tileIdx = 2; break; case 3: tileIdx = 3; break;
        case 4: tileIdx = 4 + 2 * p; break;
        default: tileIdx = 5 + 2 * p; break;
    }
    const size_t pos = ((size_t)n << 8) + ((size_t)((kk >> 3) ^ (n & 7)) << 4) + ((size_t)(kk & 7) << 1);
    *(__half*)(g_Wp + (size_t)tileIdx * TILEB + pos) = h;
}

// ---------------------------------------------------------------------------
// Pair branch (persistent, M=64 tiles, 16 warps, patch 32x16).
// Order per tile: prefetch split -> gemm -> epilogue (red, barrier shadow)
// -> sync -> convert staged X -> sync -> fetch next+1 tile.
// ---------------------------------------------------------------------------
extern "C" __global__ void __launch_bounds__(THREADS, 1)
eaw_pair_mm(const float* __restrict__ FP, const int* __restrict__ split,
            const float* __restrict__ b2a, const float* __restrict__ b2b,
            const float* __restrict__ t2, int nTiles) {
    extern __shared__ __align__(1024) char sm[];
    const int tid = threadIdx.x;
    const uint32_t smb = smem_u32(sm);

    {   // weights: 2 tiles (65536B) linear copy
        const uint4* src = (const uint4*)g_Wp;
        uint4* dst = (uint4*)sm;
        for (int i = tid; i < 4096; i += THREADS) dst[i] = src[i];
    }
    if (tid < 128) {
        ((float*)(sm + SM_BIAS))[tid]       = b2a[tid];
        ((float*)(sm + SM_BIAS))[128 + tid] = b2b[tid];
        ((float*)(sm + SM_BIAS))[256 + tid] = t2[tid];
    }

    const int lane = tid & 31, w = tid >> 5;
    const int mBase = (w >> 3) * 32, nBase = (w & 7) * 16;
    const int q = lane >> 3, r = lane & 7;
    const float* biasA = (const float*)(sm + SM_BIAS);
    const float* biasB = biasA + 128;
    const float* tvv   = biasA + 256;
    const int grid = gridDim.x;

    // prologue
    int tile = blockIdx.x;
    stage_fetch(smb, FP + (size_t)tile * (TILE_M * F), tid);
    cpa_wait0();
    stage_convert(sm, tid);
    if (tile + grid < nTiles) stage_fetch(smb, FP + (size_t)(tile + grid) * (TILE_M * F), tid);
    __syncthreads();

    for (; tile < nTiles; tile += grid) {
        // prefetch this tile's atom indices (latency hidden under gemm)
        const int* sp = split + tile * TILE_M;
        int atomIdx[2][2];
#pragma unroll
        for (int mi = 0; mi < 2; mi++)
#pragma unroll
            for (int sub = 0; sub < 2; sub++)
                atomIdx[mi][sub] = sp[mBase + 16 * mi + (lane >> 2) + 8 * sub];

        float accA[2][2][4], accB[2][2][4];
#pragma unroll
        for (int mi = 0; mi < 2; mi++)
#pragma unroll
            for (int jj = 0; jj < 2; jj++)
#pragma unroll
                for (int kq = 0; kq < 4; kq++) { accA[mi][jj][kq] = 0.f; accB[mi][jj][kq] = 0.f; }

        gemm_uni(smb, smb + SM_XH, smb + SM_XL, mBase, nBase, r, q, accA, accB);

        // epilogue immediately after gemm: reds drain in barrier-wait shadow
#pragma unroll
        for (int mi = 0; mi < 2; mi++)
#pragma unroll
            for (int sub = 0; sub < 2; sub++) {
                float* dst = g_PS + (size_t)atomIdx[mi][sub] * F;
#pragma unroll
                for (int jj = 0; jj < 2; jj++) {
                    const int c = nBase + 8 * jj + 2 * (lane & 3);
                    const float v0 = fmaxf(tvv[c]     * (accA[mi][jj][2 * sub]     + biasA[c])     * (accB[mi][jj][2 * sub]     + biasB[c]),     0.f);
                    const float v1 = fmaxf(tvv[c + 1] * (accA[mi][jj][2 * sub + 1] + biasA[c + 1]) * (accB[mi][jj][2 * sub + 1] + biasB[c + 1]), 0.f);
                    red_v2(dst + c, v0, v1);
                }
            }

        const int nt = tile + grid;
        __syncthreads();                    // all XH/XL reads of this tile done
        if (nt < nTiles) {
            cpa_wait0();                    // X(nt) staged
            stage_convert(sm, tid);         // stage -> XH/XL
        }
        __syncthreads();                    // converts visible; stage free
        if (nt + grid < nTiles)
            stage_fetch(smb, FP + (size_t)(nt + grid) * (TILE_M * F), tid);
    }
}

// ---------------------------------------------------------------------------
// Atom layer 1: g_AA = relu(t1*(FA@W1a+b1a)*(FA@W1b+b1b)). 128 CTAs x 64 rows.
// ---------------------------------------------------------------------------
extern "C" __global__ void __launch_bounds__(THREADS, 1)
eaw_atom1_mm(const float* __restrict__ FA,
             const float* __restrict__ b1a, const float* __restrict__ b1b,
             const float* __restrict__ t1) {
    extern __shared__ __align__(1024) char sm[];
    const int tid = threadIdx.x;
    const uint32_t smb = smem_u32(sm);
    {
        const uint4* src = (const uint4*)(g_Wp + 2 * TILEB);
        uint4* dst = (uint4*)sm;
        for (int i = tid; i < 4096; i += THREADS) dst[i] = src[i];
    }
    if (tid < 128) {
        ((float*)(sm + SM_BIAS))[tid]       = b1a[tid];
        ((float*)(sm + SM_BIAS))[128 + tid] = b1b[tid];
        ((float*)(sm + SM_BIAS))[256 + tid] = t1[tid];
    }
    {
        const float4* src = (const float4*)(FA + (size_t)blockIdx.x * (TILE_M * F));
        float4 xv[4];
#pragma unroll
        for (int qq = 0; qq < 4; qq++) xv[qq] = src[tid + qq * THREADS];
#pragma unroll
        for (int qq = 0; qq < 4; qq++) x_store(sm, tid + qq * THREADS, xv[qq]);
    }
    __syncthreads();

    const int lane = tid & 31, w = tid >> 5;
    const int mBase = (w >> 3) * 32, nBase = (w & 7) * 16;
    const int q = lane >> 3, r = lane & 7;
    const float* biasA = (const float*)(sm + SM_BIAS);
    const float* biasB = biasA + 128;
    const float* tvv   = biasA + 256;

    float accA[2][2][4], accB[2][2][4];
#pragma unroll
    for (int mi = 0; mi < 2; mi++)
#pragma unroll
        for (int jj = 0; jj < 2; jj++)
#pragma unroll
            for (int kq = 0; kq < 4; kq++) { accA[mi][jj][kq] = 0.f; accB[mi][jj][kq] = 0.f; }

    gemm_uni(smb, smb + SM_XH, smb + SM_XL, mBase, nBase, r, q, accA, accB);

    float* base = g_AA + (size_t)blockIdx.x * (TILE_M * F);
#pragma unroll
    for (int mi = 0; mi < 2; mi++)
#pragma unroll
        for (int sub = 0; sub < 2; sub++) {
            const int row = mBase + 16 * mi + (lane >> 2) + 8 * sub;
#pragma unroll
            for (int jj = 0; jj < 2; jj++) {
                const int c = nBase + 8 * jj + 2 * (lane & 3);
                float2 v;
                v.x = fmaxf(tvv[c]     * (accA[mi][jj][2 * sub]     + biasA[c])     * (accB[mi][jj][2 * sub]     + biasB[c]),     0.f);
                v.y = fmaxf(tvv[c + 1] * (accA[mi][jj][2 * sub + 1] + biasA[c + 1]) * (accB[mi][jj][2 * sub + 1] + biasB[c + 1]), 0.f);
                *(float2*)(base + (size_t)row * F + c) = v;
            }
        }
}

// ---------------------------------------------------------------------------
// Final layer (K=256, two phases): out = relu(t3*([AA|PS]@W3a+b3a)*(...b)).
// 128 CTAs x 64 rows.
// ---------------------------------------------------------------------------
extern "C" __global__ void __launch_bounds__(THREADS, 1)
eaw_atom2_mm(const float* __restrict__ b3a, const float* __restrict__ b3b,
             const float* __restrict__ t3, float* __restrict__ out) {
    extern __shared__ __align__(1024) char sm[];
    const int tid = threadIdx.x;
    const uint32_t smb = smem_u32(sm);
    if (tid < 128) {
        ((float*)(sm + SM_BIAS))[tid]       = b3a[tid];
        ((float*)(sm + SM_BIAS))[128 + tid] = b3b[tid];
        ((float*)(sm + SM_BIAS))[256 + tid] = t3[tid];
    }
    const int lane = tid & 31, w = tid >> 5;
    const int mBase = (w >> 3) * 32, nBase = (w & 7) * 16;
    const int q = lane >> 3, r = lane & 7;
    const float* biasA = (const float*)(sm + SM_BIAS);
    const float* biasB = biasA + 128;
    const float* tvv   = biasA + 256;

    float accA[2][2][4], accB[2][2][4];
#pragma unroll
    for (int mi = 0; mi < 2; mi++)
#pragma unroll
        for (int jj = 0; jj < 2; jj++)
#pragma unroll
            for (int kq = 0; kq < 4; kq++) { accA[mi][jj][kq] = 0.f; accB[mi][jj][kq] = 0.f; }

#pragma unroll 1
    for (int p = 0; p < 2; p++) {
        if (p) __syncthreads();             // previous phase's smem reads done
        {
            const uint4* src = (const uint4*)(g_Wp + (size_t)(4 + 2 * p) * TILEB);
            uint4* dst = (uint4*)sm;
            for (int i = tid; i < 4096; i += THREADS) dst[i] = src[i];
        }
        {
            const float4* src = (const float4*)((p == 0 ? g_AA : g_PS) + (size_t)blockIdx.x * (TILE_M * F));
            float4 xv[4];
#pragma unroll
            for (int qq = 0; qq < 4; qq++) xv[qq] = src[tid + qq * THREADS];
#pragma unroll
            for (int qq = 0; qq < 4; qq++) x_store(sm, tid + qq * THREADS, xv[qq]);
        }
        __syncthreads();
        gemm_uni(smb, smb + SM_XH, smb + SM_XL, mBase, nBase, r, q, accA, accB);
    }

    float* base = out + (size_t)blockIdx.x * (TILE_M * F);
#pragma unroll
    for (int mi = 0; mi < 2; mi++)
#pragma unroll
        for (int sub = 0; sub < 2; sub++) {
            const int row = mBase + 16 * mi + (lane >> 2) + 8 * sub;
#pragma unroll
            for (int jj = 0; jj < 2; jj++) {
                const int c = nBase + 8 * jj + 2 * (lane & 3);
                float2 v;
                v.x = fmaxf(tvv[c]     * (accA[mi][jj][2 * sub]     + biasA[c])     * (accB[mi][jj][2 * sub]     + biasB[c]),     0.f);
                v.y = fmaxf(tvv[c + 1] * (accA[mi][jj][2 * sub + 1] + biasA[c + 1]) * (accB[mi][jj][2 * sub + 1] + biasB[c + 1]), 0.f);
                *(float2*)(base + (size_t)row * F + c) = v;
            }
        }
}

// ---------------------------------------------------------------------------
// Launch
// ---------------------------------------------------------------------------
extern "C" void kernel_launch(void* const* d_in, const int* in_sizes, int n_in,
                              void* d_out, int out_size) {
    const float* FA  = (const float*)d_in[0];
    const float* FP  = (const float*)d_in[1];
    const int*   sp  = (const int*)  d_in[2];
    const float* W1a = (const float*)d_in[3];
    const float* b1a = (const float*)d_in[4];
    const float* W1b = (const float*)d_in[5];
    const float* b1b = (const float*)d_in[6];
    const float* t1  = (const float*)d_in[7];
    const float* W2a = (const float*)d_in[8];
    const float* b2a = (const float*)d_in[9];
    const float* W2b = (const float*)d_in[10];
    const float* b2b = (const float*)d_in[11];
    const float* t2  = (const float*)d_in[12];
    const float* W3a = (const float*)d_in[13];
    const float* b3a = (const float*)d_in[14];
    const float* W3b = (const float*)d_in[15];
    const float* b3b = (const float*)d_in[16];
    const float* t3  = (const float*)d_in[17];
    float* out = (float*)d_out;

    const int nPairs    = in_sizes[1] / F;             // 524288
    const int pairTiles = nPairs / TILE_M;             // 8192
    const int atomTiles = (in_sizes[0] / F) / TILE_M;  // 128

    cudaFuncSetAttribute(eaw_pair_mm,  cudaFuncAttributeMaxDynamicSharedMemorySize, SMEM_BYTES);
    cudaFuncSetAttribute(eaw_atom1_mm, cudaFuncAttributeMaxDynamicSharedMemorySize, SMEM_BYTES);
    cudaFuncSetAttribute(eaw_atom2_mm, cudaFuncAttributeMaxDynamicSharedMemorySize, SMEM_BYTES);

    int nsm = 148;
    cudaDeviceGetAttribute(&nsm, cudaDevAttrMultiProcessorCount, 0);

    eaw_prep<<<512, 256>>>(W1a, W1b, W2a, W2b, W3a, W3b);
    eaw_pair_mm<<<nsm, THREADS, SMEM_BYTES>>>(FP, sp, b2a, b2b, t2, pairTiles);
    eaw_atom1_mm<<<atomTiles, THREADS, SMEM_BYTES>>>(FA, b1a, b1b, t1);
    eaw_atom2_mm<<<atomTiles, THREADS, SMEM_BYTES>>>(b3a, b3b, t3, out);
}

// round 12
// speedup vs baseline: 1.5372x; 1.0658x over previous
#include <cuda_runtime.h>
#include <cuda_fp16.h>
#include <cstdint>

#define F        128
#define THREADS  512
#define N_ATOMS  8192
#define TILE_M   64
#define TILEB    32768        // weight tile: 128 rows * 256B (fp16, swizzled)

// ---------------------------------------------------------------------------
// Device-global scratch (no allocations allowed)
// ---------------------------------------------------------------------------
__device__ float g_PS[N_ATOMS * F];   // segment-summed pair activations
__device__ float g_AA[N_ATOMS * F];   // atom layer-1 output
// Prepped weights: fp16 (round-to-nearest), B-orientation [n][k], 256B rows,
// XOR-swizzled chunks. 8 tiles of 32768B:
//  0:W2a 1:W2b  2:W1a 3:W1b  4:W3a_c0 5:W3b_c0  6:W3a_c1 7:W3b_c1
__device__ __align__(256) unsigned char g_Wp[8 * TILEB];

// SMEM map (dynamic, base 1024-aligned):
//  [0,65536)        2 weight tiles (a, b) of 32KB
//  [65536,81920)    X hi buf0   [81920,98304)   X lo buf0
//  [98304,114688)   X hi buf1   [114688,131072) X lo buf1
//  [131072,132608)  bias: ba[128], bb[128], t[128]
#define SM_XH0   65536
#define SM_XL0   81920
#define SM_XH1   98304
#define SM_XL1   114688
#define SM_BIAS  131072
#define SMEM_BYTES 132608

// ---------------------------------------------------------------------------
// PTX helpers
// ---------------------------------------------------------------------------
__device__ __forceinline__ uint32_t smem_u32(const void* p) {
    uint32_t a;
    asm("{ .reg .u64 t; cvta.to.shared.u64 t, %1; cvt.u32.u64 %0, t; }" : "=r"(a) : "l"(p));
    return a;
}
__device__ __forceinline__ void ldmx4(uint32_t* r, uint32_t addr) {
    asm volatile("ldmatrix.sync.aligned.m8n8.x4.shared.b16 {%0,%1,%2,%3}, [%4];"
                 : "=r"(r[0]), "=r"(r[1]), "=r"(r[2]), "=r"(r[3]) : "r"(addr));
}
__device__ __forceinline__ void mma16816(float* d, const uint32_t* a, uint32_t b0, uint32_t b1) {
    asm volatile(
        "mma.sync.aligned.m16n8k16.row.col.f32.f16.f16.f32 "
        "{%0,%1,%2,%3}, {%4,%5,%6,%7}, {%8,%9}, {%0,%1,%2,%3};"
        : "+f"(d[0]), "+f"(d[1]), "+f"(d[2]), "+f"(d[3])
        : "r"(a[0]), "r"(a[1]), "r"(a[2]), "r"(a[3]), "r"(b0), "r"(b1));
}
__device__ __forceinline__ void red_v2(float* addr, float a, float b) {
    asm volatile("red.global.add.v2.f32 [%0], {%1,%2};"
                 :: "l"(addr), "f"(a), "f"(b) : "memory");
}

// ---------------------------------------------------------------------------
// X element store: fp32 float4 -> fp16 hi/lo at swizzled (row m, k4).
// i = float4 index in [0,2048): m = i>>5 in [0,64), k4 = (i&31)*4.
// Layout: 256B rows; 16B chunk c holds k in [8c,8c+8) at chunk (c ^ (m&7)).
// Xh+Xl reproduces X to ~2^-22 relative, so X @ W_fp16 is the only error.
// ---------------------------------------------------------------------------
union H2U { __half2 h; uint32_t u; };

__device__ __forceinline__ void x_store(char* sm, uint32_t xh_off, uint32_t xl_off,
                                        int i, float4 v) {
    const int m = i >> 5, k4 = (i & 31) << 2;
    const uint32_t sw = (uint32_t)(m << 8) + ((uint32_t)(((k4 >> 3) ^ (m & 7))) << 4)
                      + ((uint32_t)((k4 >> 2) & 1) << 3);
    __half2 h0 = __floats2half2_rn(v.x, v.y);
    __half2 h1 = __floats2half2_rn(v.z, v.w);
    float2 f0 = __half22float2(h0), f1 = __half22float2(h1);
    __half2 l0 = __floats2half2_rn(v.x - f0.x, v.y - f0.y);
    __half2 l1 = __floats2half2_rn(v.z - f1.x, v.w - f1.y);
    H2U a, b, c, d; a.h = h0; b.h = h1; c.h = l0; d.h = l1;
    *(uint2*)(sm + xh_off + sw) = make_uint2(a.u, b.u);
    *(uint2*)(sm + xl_off + sw) = make_uint2(c.u, d.u);
}

// ---------------------------------------------------------------------------
// 2-term GEMM for both denses, single k-loop, double-buffered fragments.
// Weight tiles at wBase (a) and wBase+32768 (b). Warp patch 32x16.
// acc layout: acc[mi][jj][4], mi in {0,1} (16-row), jj in {0,1} (8-col).
// ---------------------------------------------------------------------------
__device__ __forceinline__ void gemm_uni(uint32_t wBase, uint32_t XH, uint32_t XL,
                                         int mBase, int nBase, int r, int q,
                                         float (&accA)[2][2][4], float (&accB)[2][2][4]) {
    const int cA = q >> 1, cB = q & 1;
    const uint32_t aRow0 = (uint32_t)(mBase + r + 8 * (q & 1));
    const uint32_t bRow  = (uint32_t)(nBase + r + 8 * (q >> 1));

    uint32_t Ah[2][2][4], Al[2][2][4];
    uint32_t Ba[2][4], Bb[2][4];

#define LD_K(buf, kc) do {                                                   \
    const uint32_t oA = (uint32_t)(((cA + (kc)) ^ r) << 4);                  \
    ldmx4(Ah[buf][0], XH + (aRow0 << 8) + oA);                               \
    ldmx4(Ah[buf][1], XH + ((aRow0 + 16) << 8) + oA);                        \
    ldmx4(Al[buf][0], XL + (aRow0 << 8) + oA);                               \
    ldmx4(Al[buf][1], XL + ((aRow0 + 16) << 8) + oA);                        \
    const uint32_t oB = (bRow << 8) + (uint32_t)(((cB + (kc)) ^ r) << 4);    \
    ldmx4(Ba[buf], wBase + oB);                                              \
    ldmx4(Bb[buf], wBase + 32768 + oB);                                      \
} while (0)

    LD_K(0, 0);
#pragma unroll
    for (int k = 0; k < 8; k++) {
        const int cur = k & 1;
        if (k < 7) LD_K(cur ^ 1, 2 * (k + 1));
#pragma unroll
        for (int mi = 0; mi < 2; mi++)
#pragma unroll
            for (int jj = 0; jj < 2; jj++) {
                mma16816(accA[mi][jj], Ah[cur][mi], Ba[cur][2 * jj], Ba[cur][2 * jj + 1]);
                mma16816(accA[mi][jj], Al[cur][mi], Ba[cur][2 * jj], Ba[cur][2 * jj + 1]);
                mma16816(accB[mi][jj], Ah[cur][mi], Bb[cur][2 * jj], Bb[cur][2 * jj + 1]);
                mma16816(accB[mi][jj], Al[cur][mi], Bb[cur][2 * jj], Bb[cur][2 * jj + 1]);
            }
    }
#undef LD_K
}

// ---------------------------------------------------------------------------
// Weight prep (+ zero g_PS): fp16 round-to-nearest, B-orientation, swizzled.
// 512 blocks x 256 threads = 131072 elements.
// ---------------------------------------------------------------------------
extern "C" __global__ void eaw_prep(const float* __restrict__ W1a, const float* __restrict__ W1b,
                                    const float* __restrict__ W2a, const float* __restrict__ W2b,
                                    const float* __restrict__ W3a, const float* __restrict__ W3b) {
    const int e = blockIdx.x * blockDim.x + threadIdx.x;
    ((float4*)g_PS)[e]          = make_float4(0.f, 0.f, 0.f, 0.f);
    ((float4*)g_PS)[e + 131072] = make_float4(0.f, 0.f, 0.f, 0.f);

    int mat, off;
    if (e < 65536) { mat = e >> 14; off = e & 16383; }
    else           { int e2 = e - 65536; mat = 4 + (e2 >> 15); off = e2 & 32767; }
    const float* W;
    switch (mat) {
        case 0: W = W2a; break; case 1: W = W2b; break;
        case 2: W = W1a; break; case 3: W = W1b; break;
        case 4: W = W3a; break; default: W = W3b; break;
    }
    const int n = off & 127, k = off >> 7;     // W[k][n] at W[off] (coalesced)
    const __half h = __float2half_rn(W[off]);
    const int p = k >> 7, kk = k & 127;
    int tileIdx;
    switch (mat) {
        case 0: tileIdx = 0; break; case 1: tileIdx = 1; break;
        case 2: tileIdx = 2; break; case 3: tileIdx = 3; break;
        case 4: tileIdx = 4 + 2 * p; break;
        default: tileIdx = 5 + 2 * p; break;
    }
    const size_t pos = ((size_t)n << 8) + ((size_t)((kk >> 3) ^ (n & 7)) << 4) + ((size_t)(kk & 7) << 1);
    *(__half*)(g_Wp + (size_t)tileIdx * TILEB + pos) = h;
}

// ---------------------------------------------------------------------------
// Pair branch (persistent, M=64 tiles, 16 warps, patch 32x16).
// X double-buffered in smem; next tile's X carried in registers through the
// gemm (LDG latency hidden); ONE barrier per tile.
// ---------------------------------------------------------------------------
extern "C" __global__ void __launch_bounds__(THREADS, 1)
eaw_pair_mm(const float* __restrict__ FP, const int* __restrict__ split,
            const float* __restrict__ b2a, const float* __restrict__ b2b,
            const float* __restrict__ t2, int nTiles) {
    extern __shared__ __align__(1024) char sm[];
    const int tid = threadIdx.x;
    const uint32_t smb = smem_u32(sm);

    {   // weights: 2 tiles (65536B) linear copy
        const uint4* src = (const uint4*)g_Wp;
        uint4* dst = (uint4*)sm;
        for (int i = tid; i < 4096; i += THREADS) dst[i] = src[i];
    }
    if (tid < 128) {
        ((float*)(sm + SM_BIAS))[tid]       = b2a[tid];
        ((float*)(sm + SM_BIAS))[128 + tid] = b2b[tid];
        ((float*)(sm + SM_BIAS))[256 + tid] = t2[tid];
    }

    const int lane = tid & 31, w = tid >> 5;
    const int mBase = (w >> 3) * 32, nBase = (w & 7) * 16;
    const int q = lane >> 3, r = lane & 7;
    const float* biasA = (const float*)(sm + SM_BIAS);
    const float* biasB = biasA + 128;
    const float* tvv   = biasA + 256;
    const int grid = gridDim.x;

    const uint32_t xhOff[2] = {SM_XH0, SM_XH1};
    const uint32_t xlOff[2] = {SM_XL0, SM_XL1};

    // prologue: X(tile0) straight to buf0
    int tile = blockIdx.x;
    {
        const float4* src = (const float4*)(FP + (size_t)tile * (TILE_M * F));
#pragma unroll
        for (int qq = 0; qq < 4; qq++) {
            const int i = tid + qq * THREADS;
            x_store(sm, SM_XH0, SM_XL0, i, src[i]);
        }
    }
    __syncthreads();

    int b = 0;
    for (; tile < nTiles; tile += grid) {
        const int nt = tile + grid;
        const bool haveNext = nt < nTiles;

        // next tile's X into registers (LDG latency hidden under gemm)
        float4 xv[4];
        if (haveNext) {
            const float4* src = (const float4*)(FP + (size_t)nt * (TILE_M * F));
#pragma unroll
            for (int qq = 0; qq < 4; qq++) xv[qq] = src[tid + qq * THREADS];
        }
        // this tile's atom indices (hidden under gemm)
        const int* sp = split + tile * TILE_M;
        int atomIdx[2][2];
#pragma unroll
        for (int mi = 0; mi < 2; mi++)
#pragma unroll
            for (int sub = 0; sub < 2; sub++)
                atomIdx[mi][sub] = sp[mBase + 16 * mi + (lane >> 2) + 8 * sub];

        float accA[2][2][4], accB[2][2][4];
#pragma unroll
        for (int mi = 0; mi < 2; mi++)
#pragma unroll
            for (int jj = 0; jj < 2; jj++)
#pragma unroll
                for (int kq = 0; kq < 4; kq++) { accA[mi][jj][kq] = 0.f; accB[mi][jj][kq] = 0.f; }

        gemm_uni(smb, smb + xhOff[b], smb + xlOff[b], mBase, nBase, r, q, accA, accB);

        // epilogue right after gemm: reds drain while other warps still gemm
#pragma unroll
        for (int mi = 0; mi < 2; mi++)
#pragma unroll
            for (int sub = 0; sub < 2; sub++) {
                float* dst = g_PS + (size_t)atomIdx[mi][sub] * F;
#pragma unroll
                for (int jj = 0; jj < 2; jj++) {
                    const int c = nBase + 8 * jj + 2 * (lane & 3);
                    const float v0 = fmaxf(tvv[c]     * (accA[mi][jj][2 * sub]     + biasA[c])     * (accB[mi][jj][2 * sub]     + biasB[c]),     0.f);
                    const float v1 = fmaxf(tvv[c + 1] * (accA[mi][jj][2 * sub + 1] + biasA[c + 1]) * (accB[mi][jj][2 * sub + 1] + biasB[c + 1]), 0.f);
                    red_v2(dst + c, v0, v1);
                }
            }

        // convert next tile into the other buffer, then the single barrier
        if (haveNext) {
#pragma unroll
            for (int qq = 0; qq < 4; qq++)
                x_store(sm, xhOff[b ^ 1], xlOff[b ^ 1], tid + qq * THREADS, xv[qq]);
        }
        __syncthreads();
        b ^= 1;
    }
}

// ---------------------------------------------------------------------------
// Atom layer 1: g_AA = relu(t1*(FA@W1a+b1a)*(FA@W1b+b1b)). 128 CTAs x 64 rows.
// ---------------------------------------------------------------------------
extern "C" __global__ void __launch_bounds__(THREADS, 1)
eaw_atom1_mm(const float* __restrict__ FA,
             const float* __restrict__ b1a, const float* __restrict__ b1b,
             const float* __restrict__ t1) {
    extern __shared__ __align__(1024) char sm[];
    const int tid = threadIdx.x;
    const uint32_t smb = smem_u32(sm);
    {
        const uint4* src = (const uint4*)(g_Wp + 2 * TILEB);
        uint4* dst = (uint4*)sm;
        for (int i = tid; i < 4096; i += THREADS) dst[i] = src[i];
    }
    if (tid < 128) {
        ((float*)(sm + SM_BIAS))[tid]       = b1a[tid];
        ((float*)(sm + SM_BIAS))[128 + tid] = b1b[tid];
        ((float*)(sm + SM_BIAS))[256 + tid] = t1[tid];
    }
    {
        const float4* src = (const float4*)(FA + (size_t)blockIdx.x * (TILE_M * F));
        float4 xv[4];
#pragma unroll
        for (int qq = 0; qq < 4; qq++) xv[qq] = src[tid + qq * THREADS];
#pragma unroll
        for (int qq = 0; qq < 4; qq++) x_store(sm, SM_XH0, SM_XL0, tid + qq * THREADS, xv[qq]);
    }
    __syncthreads();

    const int lane = tid & 31, w = tid >> 5;
    const int mBase = (w >> 3) * 32, nBase = (w & 7) * 16;
    const int q = lane >> 3, r = lane & 7;
    const float* biasA = (const float*)(sm + SM_BIAS);
    const float* biasB = biasA + 128;
    const float* tvv   = biasA + 256;

    float accA[2][2][4], accB[2][2][4];
#pragma unroll
    for (int mi = 0; mi < 2; mi++)
#pragma unroll
        for (int jj = 0; jj < 2; jj++)
#pragma unroll
            for (int kq = 0; kq < 4; kq++) { accA[mi][jj][kq] = 0.f; accB[mi][jj][kq] = 0.f; }

    gemm_uni(smb, smb + SM_XH0, smb + SM_XL0, mBase, nBase, r, q, accA, accB);

    float* base = g_AA + (size_t)blockIdx.x * (TILE_M * F);
#pragma unroll
    for (int mi = 0; mi < 2; mi++)
#pragma unroll
        for (int sub = 0; sub < 2; sub++) {
            const int row = mBase + 16 * mi + (lane >> 2) + 8 * sub;
#pragma unroll
            for (int jj = 0; jj < 2; jj++) {
                const int c = nBase + 8 * jj + 2 * (lane & 3);
                float2 v;
                v.x = fmaxf(tvv[c]     * (accA[mi][jj][2 * sub]     + biasA[c])     * (accB[mi][jj][2 * sub]     + biasB[c]),     0.f);
                v.y = fmaxf(tvv[c + 1] * (accA[mi][jj][2 * sub + 1] + biasA[c + 1]) * (accB[mi][jj][2 * sub + 1] + biasB[c + 1]), 0.f);
                *(float2*)(base + (size_t)row * F + c) = v;
            }
        }
}

// ---------------------------------------------------------------------------
// Final layer (K=256, two phases): out = relu(t3*([AA|PS]@W3a+b3a)*(...b)).
// 128 CTAs x 64 rows.
// ---------------------------------------------------------------------------
extern "C" __global__ void __launch_bounds__(THREADS, 1)
eaw_atom2_mm(const float* __restrict__ b3a, const float* __restrict__ b3b,
             const float* __restrict__ t3, float* __restrict__ out) {
    extern __shared__ __align__(1024) char sm[];
    const int tid = threadIdx.x;
    const uint32_t smb = smem_u32(sm);
    if (tid < 128) {
        ((float*)(sm + SM_BIAS))[tid]       = b3a[tid];
        ((float*)(sm + SM_BIAS))[128 + tid] = b3b[tid];
        ((float*)(sm + SM_BIAS))[256 + tid] = t3[tid];
    }
    const int lane = tid & 31, w = tid >> 5;
    const int mBase = (w >> 3) * 32, nBase = (w & 7) * 16;
    const int q = lane >> 3, r = lane & 7;
    const float* biasA = (const float*)(sm + SM_BIAS);
    const float* biasB = biasA + 128;
    const float* tvv   = biasA + 256;

    float accA[2][2][4], accB[2][2][4];
#pragma unroll
    for (int mi = 0; mi < 2; mi++)
#pragma unroll
        for (int jj = 0; jj < 2; jj++)
#pragma unroll
            for (int kq = 0; kq < 4; kq++) { accA[mi][jj][kq] = 0.f; accB[mi][jj][kq] = 0.f; }

#pragma unroll 1
    for (int p = 0; p < 2; p++) {
        if (p) __syncthreads();             // previous phase's smem reads done
        {
            const uint4* src = (const uint4*)(g_Wp + (size_t)(4 + 2 * p) * TILEB);
            uint4* dst = (uint4*)sm;
            for (int i = tid; i < 4096; i += THREADS) dst[i] = src[i];
        }
        {
            const float4* src = (const float4*)((p == 0 ? g_AA : g_PS) + (size_t)blockIdx.x * (TILE_M * F));
            float4 xv[4];
#pragma unroll
            for (int qq = 0; qq < 4; qq++) xv[qq] = src[tid + qq * THREADS];
#pragma unroll
            for (int qq = 0; qq < 4; qq++) x_store(sm, SM_XH0, SM_XL0, tid + qq * THREADS, xv[qq]);
        }
        __syncthreads();
        gemm_uni(smb, smb + SM_XH0, smb + SM_XL0, mBase, nBase, r, q, accA, accB);
    }

    float* base = out + (size_t)blockIdx.x * (TILE_M * F);
#pragma unroll
    for (int mi = 0; mi < 2; mi++)
#pragma unroll
        for (int sub = 0; sub < 2; sub++) {
            const int row = mBase + 16 * mi + (lane >> 2) + 8 * sub;
#pragma unroll
            for (int jj = 0; jj < 2; jj++) {
                const int c = nBase + 8 * jj + 2 * (lane & 3);
                float2 v;
                v.x = fmaxf(tvv[c]     * (accA[mi][jj][2 * sub]     + biasA[c])     * (accB[mi][jj][2 * sub]     + biasB[c]),     0.f);
                v.y = fmaxf(tvv[c + 1] * (accA[mi][jj][2 * sub + 1] + biasA[c + 1]) * (accB[mi][jj][2 * sub + 1] + biasB[c + 1]), 0.f);
                *(float2*)(base + (size_t)row * F + c) = v;
            }
        }
}

// ---------------------------------------------------------------------------
// Launch
// ---------------------------------------------------------------------------
extern "C" void kernel_launch(void* const* d_in, const int* in_sizes, int n_in,
                              void* d_out, int out_size) {
    const float* FA  = (const float*)d_in[0];
    const float* FP  = (const float*)d_in[1];
    const int*   sp  = (const int*)  d_in[2];
    const float* W1a = (const float*)d_in[3];
    const float* b1a = (const float*)d_in[4];
    const float* W1b = (const float*)d_in[5];
    const float* b1b = (const float*)d_in[6];
    const float* t1  = (const float*)d_in[7];
    const float* W2a = (const float*)d_in[8];
    const float* b2a = (const float*)d_in[9];
    const float* W2b = (const float*)d_in[10];
    const float* b2b = (const float*)d_in[11];
    const float* t2  = (const float*)d_in[12];
    const float* W3a = (const float*)d_in[13];
    const float* b3a = (const float*)d_in[14];
    const float* W3b = (const float*)d_in[15];
    const float* b3b = (const float*)d_in[16];
    const float* t3  = (const float*)d_in[17];
    float* out = (float*)d_out;

    const int nPairs    = in_sizes[1] / F;             // 524288
    const int pairTiles = nPairs / TILE_M;             // 8192
    const int atomTiles = (in_sizes[0] / F) / TILE_M;  // 128

    cudaFuncSetAttribute(eaw_pair_mm,  cudaFuncAttributeMaxDynamicSharedMemorySize, SMEM_BYTES);
    cudaFuncSetAttribute(eaw_atom1_mm, cudaFuncAttributeMaxDynamicSharedMemorySize, SMEM_BYTES);
    cudaFuncSetAttribute(eaw_atom2_mm, cudaFuncAttributeMaxDynamicSharedMemorySize, SMEM_BYTES);

    int nsm = 148;
    cudaDeviceGetAttribute(&nsm, cudaDevAttrMultiProcessorCount, 0);

    eaw_prep<<<512, 256>>>(W1a, W1b, W2a, W2b, W3a, W3b);
    eaw_pair_mm<<<nsm, THREADS, SMEM_BYTES>>>(FP, sp, b2a, b2b, t2, pairTiles);
    eaw_atom1_mm<<<atomTiles, THREADS, SMEM_BYTES>>>(FA, b1a, b1b, t1);
    eaw_atom2_mm<<<atomTiles, THREADS, SMEM_BYTES>>>(b3a, b3b, t3, out);
}

// round 13
// speedup vs baseline: 2.0112x; 1.3083x over previous
#include <cuda_runtime.h>
#include <cuda_fp16.h>
#include <cstdint>

#define F        128
#define THREADS  512
#define N_ATOMS  8192
#define TILE_M   64
#define TILEB    32768        // weight tile: 128 rows * 256B (fp16, swizzled)

// ---------------------------------------------------------------------------
// Device-global scratch (no allocations allowed)
// ---------------------------------------------------------------------------
__device__ float g_PS[N_ATOMS * F];   // segment-summed pair activations
__device__ float g_AA[N_ATOMS * F];   // atom layer-1 output
// Prepped weights: fp16 (round-to-nearest), B-orientation [n][k], 256B rows,
// XOR-swizzled chunks. 8 tiles of 32768B:
//  0:W2a 1:W2b  2:W1a 3:W1b  4:W3a_c0 5:W3b_c0  6:W3a_c1 7:W3b_c1
__device__ __align__(256) unsigned char g_Wp[8 * TILEB];

// SMEM map (dynamic, base 1024-aligned):
//  [0,65536)       2 weight tiles (a, b) of 32KB
//  [65536,81920)   X buf0 (fp16, 64 rows x 256B)
//  [81920,98304)   X buf1
//  [98304,99840)   bias: ba[128], bb[128], t[128]
#define SM_X0    65536
#define SM_X1    81920
#define SM_BIAS  98304
#define SMEM_BYTES 99840

// ---------------------------------------------------------------------------
// PTX helpers
// ---------------------------------------------------------------------------
__device__ __forceinline__ uint32_t smem_u32(const void* p) {
    uint32_t a;
    asm("{ .reg .u64 t; cvta.to.shared.u64 t, %1; cvt.u32.u64 %0, t; }" : "=r"(a) : "l"(p));
    return a;
}
__device__ __forceinline__ void ldmx4(uint32_t* r, uint32_t addr) {
    asm volatile("ldmatrix.sync.aligned.m8n8.x4.shared.b16 {%0,%1,%2,%3}, [%4];"
                 : "=r"(r[0]), "=r"(r[1]), "=r"(r[2]), "=r"(r[3]) : "r"(addr));
}
__device__ __forceinline__ void mma16816(float* d, const uint32_t* a, uint32_t b0, uint32_t b1) {
    asm volatile(
        "mma.sync.aligned.m16n8k16.row.col.f32.f16.f16.f32 "
        "{%0,%1,%2,%3}, {%4,%5,%6,%7}, {%8,%9}, {%0,%1,%2,%3};"
        : "+f"(d[0]), "+f"(d[1]), "+f"(d[2]), "+f"(d[3])
        : "r"(a[0]), "r"(a[1]), "r"(a[2]), "r"(a[3]), "r"(b0), "r"(b1));
}
__device__ __forceinline__ void red_v2(float* addr, float a, float b) {
    asm volatile("red.global.add.v2.f32 [%0], {%1,%2};"
                 :: "l"(addr), "f"(a), "f"(b) : "memory");
}

// ---------------------------------------------------------------------------
// X element store: fp32 float4 -> fp16 (round-to-nearest) at swizzled (m, k4).
// i = float4 index in [0,2048): m = i>>5 in [0,64), k4 = (i&31)*4.
// Layout: 256B rows; 16B chunk c holds k in [8c,8c+8) at chunk (c ^ (m&7)).
// ---------------------------------------------------------------------------
union H2U { __half2 h; uint32_t u; };

__device__ __forceinline__ void x_store(char* sm, uint32_t x_off, int i, float4 v) {
    const int m = i >> 5, k4 = (i & 31) << 2;
    const uint32_t sw = (uint32_t)(m << 8) + ((uint32_t)(((k4 >> 3) ^ (m & 7))) << 4)
                      + ((uint32_t)((k4 >> 2) & 1) << 3);
    H2U a, b;
    a.h = __floats2half2_rn(v.x, v.y);
    b.h = __floats2half2_rn(v.z, v.w);
    *(uint2*)(sm + x_off + sw) = make_uint2(a.u, b.u);
}

// ---------------------------------------------------------------------------
// Plain fp16 GEMM for both denses, single k-loop, double-buffered fragments.
// Weight tiles at wBase (a) and wBase+32768 (b). Warp patch 32x16.
// acc layout: acc[mi][jj][4], mi in {0,1} (16-row), jj in {0,1} (8-col).
// ---------------------------------------------------------------------------
__device__ __forceinline__ void gemm_uni(uint32_t wBase, uint32_t X,
                                         int mBase, int nBase, int r, int q,
                                         float (&accA)[2][2][4], float (&accB)[2][2][4]) {
    const int cA = q >> 1, cB = q & 1;
    const uint32_t aRow0 = (uint32_t)(mBase + r + 8 * (q & 1));
    const uint32_t bRow  = (uint32_t)(nBase + r + 8 * (q >> 1));

    uint32_t Ah[2][2][4];
    uint32_t Ba[2][4], Bb[2][4];

#define LD_K(buf, kc) do {                                                   \
    const uint32_t oA = (uint32_t)(((cA + (kc)) ^ r) << 4);                  \
    ldmx4(Ah[buf][0], X + (aRow0 << 8) + oA);                                \
    ldmx4(Ah[buf][1], X + ((aRow0 + 16) << 8) + oA);                         \
    const uint32_t oB = (bRow << 8) + (uint32_t)(((cB + (kc)) ^ r) << 4);    \
    ldmx4(Ba[buf], wBase + oB);                                              \
    ldmx4(Bb[buf], wBase + 32768 + oB);                                      \
} while (0)

    LD_K(0, 0);
#pragma unroll
    for (int k = 0; k < 8; k++) {
        const int cur = k & 1;
        if (k < 7) LD_K(cur ^ 1, 2 * (k + 1));
#pragma unroll
        for (int mi = 0; mi < 2; mi++)
#pragma unroll
            for (int jj = 0; jj < 2; jj++) {
                mma16816(accA[mi][jj], Ah[cur][mi], Ba[cur][2 * jj], Ba[cur][2 * jj + 1]);
                mma16816(accB[mi][jj], Ah[cur][mi], Bb[cur][2 * jj], Bb[cur][2 * jj + 1]);
            }
    }
#undef LD_K
}

// ---------------------------------------------------------------------------
// Weight prep (+ zero g_PS): fp16 round-to-nearest, B-orientation, swizzled.
// 512 blocks x 256 threads = 131072 elements.
// ---------------------------------------------------------------------------
extern "C" __global__ void eaw_prep(const float* __restrict__ W1a, const float* __restrict__ W1b,
                                    const float* __restrict__ W2a, const float* __restrict__ W2b,
                                    const float* __restrict__ W3a, const float* __restrict__ W3b) {
    const int e = blockIdx.x * blockDim.x + threadIdx.x;
    ((float4*)g_PS)[e]          = make_float4(0.f, 0.f, 0.f, 0.f);
    ((float4*)g_PS)[e + 131072] = make_float4(0.f, 0.f, 0.f, 0.f);

    int mat, off;
    if (e < 65536) { mat = e >> 14; off = e & 16383; }
    else           { int e2 = e - 65536; mat = 4 + (e2 >> 15); off = e2 & 32767; }
    const float* W;
    switch (mat) {
        case 0: W = W2a; break; case 1: W = W2b; break;
        case 2: W = W1a; break; case 3: W = W1b; break;
        case 4: W = W3a; break; default: W = W3b; break;
    }
    const int n = off & 127, k = off >> 7;     // W[k][n] at W[off] (coalesced)
    const __half h = __float2half_rn(W[off]);
    const int p = k >> 7, kk = k & 127;
    int tileIdx;
    switch (mat) {
        case 0: tileIdx = 0; break; case 1: tileIdx = 1; break;
        case 2: tileIdx = 2; break; case 3: tileIdx = 3; break;
        case 4: tileIdx = 4 + 2 * p; break;
        default: tileIdx = 5 + 2 * p; break;
    }
    const size_t pos = ((size_t)n << 8) + ((size_t)((kk >> 3) ^ (n & 7)) << 4) + ((size_t)(kk & 7) << 1);
    *(__half*)(g_Wp + (size_t)tileIdx * TILEB + pos) = h;
}

// ---------------------------------------------------------------------------
// Pair branch (persistent, M=64 tiles, 16 warps, patch 32x16).
// X double-buffered in smem; next tile's X carried in registers through the
// gemm (LDG latency hidden); ONE barrier per tile.
// ---------------------------------------------------------------------------
extern "C" __global__ void __launch_bounds__(THREADS, 1)
eaw_pair_mm(const float* __restrict__ FP, const int* __restrict__ split,
            const float* __restrict__ b2a, const float* __restrict__ b2b,
            const float* __restrict__ t2, int nTiles) {
    extern __shared__ __align__(1024) char sm[];
    const int tid = threadIdx.x;
    const uint32_t smb = smem_u32(sm);

    {   // weights: 2 tiles (65536B) linear copy
        const uint4* src = (const uint4*)g_Wp;
        uint4* dst = (uint4*)sm;
        for (int i = tid; i < 4096; i += THREADS) dst[i] = src[i];
    }
    if (tid < 128) {
        ((float*)(sm + SM_BIAS))[tid]       = b2a[tid];
        ((float*)(sm + SM_BIAS))[128 + tid] = b2b[tid];
        ((float*)(sm + SM_BIAS))[256 + tid] = t2[tid];
    }

    const int lane = tid & 31, w = tid >> 5;
    const int mBase = (w >> 3) * 32, nBase = (w & 7) * 16;
    const int q = lane >> 3, r = lane & 7;
    const float* biasA = (const float*)(sm + SM_BIAS);
    const float* biasB = biasA + 128;
    const float* tvv   = biasA + 256;
    const int grid = gridDim.x;

    const uint32_t xOff[2] = {SM_X0, SM_X1};

    // prologue: X(tile0) straight to buf0
    int tile = blockIdx.x;
    {
        const float4* src = (const float4*)(FP + (size_t)tile * (TILE_M * F));
#pragma unroll
        for (int qq = 0; qq < 4; qq++) {
            const int i = tid + qq * THREADS;
            x_store(sm, SM_X0, i, src[i]);
        }
    }
    __syncthreads();

    int b = 0;
    for (; tile < nTiles; tile += grid) {
        const int nt = tile + grid;
        const bool haveNext = nt < nTiles;

        // next tile's X into registers (LDG latency hidden under gemm)
        float4 xv[4];
        if (haveNext) {
            const float4* src = (const float4*)(FP + (size_t)nt * (TILE_M * F));
#pragma unroll
            for (int qq = 0; qq < 4; qq++) xv[qq] = src[tid + qq * THREADS];
        }
        // this tile's atom indices (hidden under gemm)
        const int* sp = split + tile * TILE_M;
        int atomIdx[2][2];
#pragma unroll
        for (int mi = 0; mi < 2; mi++)
#pragma unroll
            for (int sub = 0; sub < 2; sub++)
                atomIdx[mi][sub] = sp[mBase + 16 * mi + (lane >> 2) + 8 * sub];

        float accA[2][2][4], accB[2][2][4];
#pragma unroll
        for (int mi = 0; mi < 2; mi++)
#pragma unroll
            for (int jj = 0; jj < 2; jj++)
#pragma unroll
                for (int kq = 0; kq < 4; kq++) { accA[mi][jj][kq] = 0.f; accB[mi][jj][kq] = 0.f; }

        gemm_uni(smb, smb + xOff[b], mBase, nBase, r, q, accA, accB);

        // epilogue right after gemm: reds drain while other warps still gemm
#pragma unroll
        for (int mi = 0; mi < 2; mi++)
#pragma unroll
            for (int sub = 0; sub < 2; sub++) {
                float* dst = g_PS + (size_t)atomIdx[mi][sub] * F;
#pragma unroll
                for (int jj = 0; jj < 2; jj++) {
                    const int c = nBase + 8 * jj + 2 * (lane & 3);
                    const float v0 = fmaxf(tvv[c]     * (accA[mi][jj][2 * sub]     + biasA[c])     * (accB[mi][jj][2 * sub]     + biasB[c]),     0.f);
                    const float v1 = fmaxf(tvv[c + 1] * (accA[mi][jj][2 * sub + 1] + biasA[c + 1]) * (accB[mi][jj][2 * sub + 1] + biasB[c + 1]), 0.f);
                    red_v2(dst + c, v0, v1);
                }
            }

        // convert next tile into the other buffer, then the single barrier
        if (haveNext) {
#pragma unroll
            for (int qq = 0; qq < 4; qq++)
                x_store(sm, xOff[b ^ 1], tid + qq * THREADS, xv[qq]);
        }
        __syncthreads();
        b ^= 1;
    }
}

// ---------------------------------------------------------------------------
// Atom layer 1: g_AA = relu(t1*(FA@W1a+b1a)*(FA@W1b+b1b)). 128 CTAs x 64 rows.
// ---------------------------------------------------------------------------
extern "C" __global__ void __launch_bounds__(THREADS, 1)
eaw_atom1_mm(const float* __restrict__ FA,
             const float* __restrict__ b1a, const float* __restrict__ b1b,
             const float* __restrict__ t1) {
    extern __shared__ __align__(1024) char sm[];
    const int tid = threadIdx.x;
    const uint32_t smb = smem_u32(sm);
    {
        const uint4* src = (const uint4*)(g_Wp + 2 * TILEB);
        uint4* dst = (uint4*)sm;
        for (int i = tid; i < 4096; i += THREADS) dst[i] = src[i];
    }
    if (tid < 128) {
        ((float*)(sm + SM_BIAS))[tid]       = b1a[tid];
        ((float*)(sm + SM_BIAS))[128 + tid] = b1b[tid];
        ((float*)(sm + SM_BIAS))[256 + tid] = t1[tid];
    }
    {
        const float4* src = (const float4*)(FA + (size_t)blockIdx.x * (TILE_M * F));
        float4 xv[4];
#pragma unroll
        for (int qq = 0; qq < 4; qq++) xv[qq] = src[tid + qq * THREADS];
#pragma unroll
        for (int qq = 0; qq < 4; qq++) x_store(sm, SM_X0, tid + qq * THREADS, xv[qq]);
    }
    __syncthreads();

    const int lane = tid & 31, w = tid >> 5;
    const int mBase = (w >> 3) * 32, nBase = (w & 7) * 16;
    const int q = lane >> 3, r = lane & 7;
    const float* biasA = (const float*)(sm + SM_BIAS);
    const float* biasB = biasA + 128;
    const float* tvv   = biasA + 256;

    float accA[2][2][4], accB[2][2][4];
#pragma unroll
    for (int mi = 0; mi < 2; mi++)
#pragma unroll
        for (int jj = 0; jj < 2; jj++)
#pragma unroll
            for (int kq = 0; kq < 4; kq++) { accA[mi][jj][kq] = 0.f; accB[mi][jj][kq] = 0.f; }

    gemm_uni(smb, smb + SM_X0, mBase, nBase, r, q, accA, accB);

    float* base = g_AA + (size_t)blockIdx.x * (TILE_M * F);
#pragma unroll
    for (int mi = 0; mi < 2; mi++)
#pragma unroll
        for (int sub = 0; sub < 2; sub++) {
            const int row = mBase + 16 * mi + (lane >> 2) + 8 * sub;
#pragma unroll
            for (int jj = 0; jj < 2; jj++) {
                const int c = nBase + 8 * jj + 2 * (lane & 3);
                float2 v;
                v.x = fmaxf(tvv[c]     * (accA[mi][jj][2 * sub]     + biasA[c])     * (accB[mi][jj][2 * sub]     + biasB[c]),     0.f);
                v.y = fmaxf(tvv[c + 1] * (accA[mi][jj][2 * sub + 1] + biasA[c + 1]) * (accB[mi][jj][2 * sub + 1] + biasB[c + 1]), 0.f);
                *(float2*)(base + (size_t)row * F + c) = v;
            }
        }
}

// ---------------------------------------------------------------------------
// Final layer (K=256, two phases): out = relu(t3*([AA|PS]@W3a+b3a)*(...b)).
// 128 CTAs x 64 rows.
// ---------------------------------------------------------------------------
extern "C" __global__ void __launch_bounds__(THREADS, 1)
eaw_atom2_mm(const float* __restrict__ b3a, const float* __restrict__ b3b,
             const float* __restrict__ t3, float* __restrict__ out) {
    extern __shared__ __align__(1024) char sm[];
    const int tid = threadIdx.x;
    const uint32_t smb = smem_u32(sm);
    if (tid < 128) {
        ((float*)(sm + SM_BIAS))[tid]       = b3a[tid];
        ((float*)(sm + SM_BIAS))[128 + tid] = b3b[tid];
        ((float*)(sm + SM_BIAS))[256 + tid] = t3[tid];
    }
    const int lane = tid & 31, w = tid >> 5;
    const int mBase = (w >> 3) * 32, nBase = (w & 7) * 16;
    const int q = lane >> 3, r = lane & 7;
    const float* biasA = (const float*)(sm + SM_BIAS);
    const float* biasB = biasA + 128;
    const float* tvv   = biasA + 256;

    float accA[2][2][4], accB[2][2][4];
#pragma unroll
    for (int mi = 0; mi < 2; mi++)
#pragma unroll
        for (int jj = 0; jj < 2; jj++)
#pragma unroll
            for (int kq = 0; kq < 4; kq++) { accA[mi][jj][kq] = 0.f; accB[mi][jj][kq] = 0.f; }

#pragma unroll 1
    for (int p = 0; p < 2; p++) {
        if (p) __syncthreads();             // previous phase's smem reads done
        {
            const uint4* src = (const uint4*)(g_Wp + (size_t)(4 + 2 * p) * TILEB);
            uint4* dst = (uint4*)sm;
            for (int i = tid; i < 4096; i += THREADS) dst[i] = src[i];
        }
        {
            const float4* src = (const float4*)((p == 0 ? g_AA : g_PS) + (size_t)blockIdx.x * (TILE_M * F));
            float4 xv[4];
#pragma unroll
            for (int qq = 0; qq < 4; qq++) xv[qq] = src[tid + qq * THREADS];
#pragma unroll
            for (int qq = 0; qq < 4; qq++) x_store(sm, SM_X0, tid + qq * THREADS, xv[qq]);
        }
        __syncthreads();
        gemm_uni(smb, smb + SM_X0, mBase, nBase, r, q, accA, accB);
    }

    float* base = out + (size_t)blockIdx.x * (TILE_M * F);
#pragma unroll
    for (int mi = 0; mi < 2; mi++)
#pragma unroll
        for (int sub = 0; sub < 2; sub++) {
            const int row = mBase + 16 * mi + (lane >> 2) + 8 * sub;
#pragma unroll
            for (int jj = 0; jj < 2; jj++) {
                const int c = nBase + 8 * jj + 2 * (lane & 3);
                float2 v;
                v.x = fmaxf(tvv[c]     * (accA[mi][jj][2 * sub]     + biasA[c])     * (accB[mi][jj][2 * sub]     + biasB[c]),     0.f);
                v.y = fmaxf(tvv[c + 1] * (accA[mi][jj][2 * sub + 1] + biasA[c + 1]) * (accB[mi][jj][2 * sub + 1] + biasB[c + 1]), 0.f);
                *(float2*)(base + (size_t)row * F + c) = v;
            }
        }
}

// ---------------------------------------------------------------------------
// Launch
// ---------------------------------------------------------------------------
extern "C" void kernel_launch(void* const* d_in, const int* in_sizes, int n_in,
                              void* d_out, int out_size) {
    const float* FA  = (const float*)d_in[0];
    const float* FP  = (const float*)d_in[1];
    const int*   sp  = (const int*)  d_in[2];
    const float* W1a = (const float*)d_in[3];
    const float* b1a = (const float*)d_in[4];
    const float* W1b = (const float*)d_in[5];
    const float* b1b = (const float*)d_in[6];
    const float* t1  = (const float*)d_in[7];
    const float* W2a = (const float*)d_in[8];
    const float* b2a = (const float*)d_in[9];
    const float* W2b = (const float*)d_in[10];
    const float* b2b = (const float*)d_in[11];
    const float* t2  = (const float*)d_in[12];
    const float* W3a = (const float*)d_in[13];
    const float* b3a = (const float*)d_in[14];
    const float* W3b = (const float*)d_in[15];
    const float* b3b = (const float*)d_in[16];
    const float* t3  = (const float*)d_in[17];
    float* out = (float*)d_out;

    const int nPairs    = in_sizes[1] / F;             // 524288
    const int pairTiles = nPairs / TILE_M;             // 8192
    const int atomTiles = (in_sizes[0] / F) / TILE_M;  // 128

    cudaFuncSetAttribute(eaw_pair_mm,  cudaFuncAttributeMaxDynamicSharedMemorySize, SMEM_BYTES);
    cudaFuncSetAttribute(eaw_atom1_mm, cudaFuncAttributeMaxDynamicSharedMemorySize, SMEM_BYTES);
    cudaFuncSetAttribute(eaw_atom2_mm, cudaFuncAttributeMaxDynamicSharedMemorySize, SMEM_BYTES);

    int nsm = 148;
    cudaDeviceGetAttribute(&nsm, cudaDevAttrMultiProcessorCount, 0);

    eaw_prep<<<512, 256>>>(W1a, W1b, W2a, W2b, W3a, W3b);
    eaw_pair_mm<<<nsm, THREADS, SMEM_BYTES>>>(FP, sp, b2a, b2b, t2, pairTiles);
    eaw_atom1_mm<<<atomTiles, THREADS, SMEM_BYTES>>>(FA, b1a, b1b, t1);
    eaw_atom2_mm<<<atomTiles, THREADS, SMEM_BYTES>>>(b3a, b3b, t3, out);
}